// round 6
// baseline (speedup 1.0000x reference)
#include <cuda_runtime.h>

// ---------------------------------------------------------------------------
// ComputeLoss (YOLOv5-style), fixed shapes:
//   p0: (32,255,80,80)  p1: (32,255,40,40)  p2: (32,255,20,20)
//   targets: (1024,6) = [img, cls, cx, cy, w, h]
// Output: one float32 scalar.
//
// SINGLE kernel:
//   blocks [0, OBJ_BLOCKS)    : dense sum of softplus(obj_logit) (3.2 MB stream)
//   blocks [OBJ_BLOCKS, GRID) : one warp per candidate (off-major order so
//                               flagged work spreads evenly across blocks);
//                               GIoU/lbox, lcls, telescoping atomicMax corr
//   last block to finish      : finalizes scalar, zeroes touched g_objmax
//                               cells via compacted list, resets state
// ---------------------------------------------------------------------------

#define NIMG 32
#define NA   3
#define NCLS 80
#define MT   1024
#define CPL  (5*NA*MT)            // 15360 candidates per level
#define TOTC (3*CPL)              // 46080
#define CELLS0 (NIMG*NA*80*80)    // 614400
#define CELLS1 (NIMG*NA*40*40)    // 153600
#define CELLS2 (NIMG*NA*20*20)    // 38400
#define CELLS_TOT (CELLS0+CELLS1+CELLS2)   // 806400

#define OBJ_GROUPS (CELLS_TOT/4)              // 201600 float4 groups
#define OBJ_BLOCKS ((OBJ_GROUPS + 255)/256)   // 788
#define CAND_BLOCKS (TOTC/8)                  // 5760
#define GRID (OBJ_BLOCKS + CAND_BLOCKS)       // 6548

__constant__ float c_anch[3][3][2] = {
  {{1.25f,1.625f},{2.0f,3.75f},{4.125f,2.875f}},
  {{1.875f,3.8125f},{3.875f,2.8125f},{3.6875f,7.4375f}},
  {{3.625f,2.8125f},{4.875f,6.1875f},{11.65625f,10.1875f}}
};

// per-cell objectness max (float bits >= 0). Zero at module load; last block
// zeroes every touched cell each launch (list-driven).
__device__ unsigned g_objmax[CELLS_TOT];
__device__ int   g_cellList[TOTC];
__device__ int   g_nflag;
__device__ int   g_done;
// [0..2]=lbox, [3..5]=cls, [6..8]=obj_softplus, [9..11]=obj_corr
__device__ double g_acc[12];
__device__ int g_cnt[3];

__device__ __forceinline__ float sp_(float x){          // softplus (fast-math)
    return fmaxf(x, 0.f) + __logf(1.f + __expf(-fabsf(x)));
}
__device__ __forceinline__ float sig_(float x){
    return 1.f / (1.f + __expf(-x));
}

__device__ __forceinline__ float giou_(float px,float py,float pw,float ph,
                                       float gx,float gy,float gw,float gh){
    const float eps = 1e-7f;
    float px1 = px - pw*0.5f, py1 = py - ph*0.5f;
    float px2 = px + pw*0.5f, py2 = py + ph*0.5f;
    float qx1 = gx - gw*0.5f, qy1 = gy - gh*0.5f;
    float qx2 = gx + gw*0.5f, qy2 = gy + gh*0.5f;
    float iw = fmaxf(fminf(px2,qx2) - fmaxf(px1,qx1), 0.f);
    float ih = fmaxf(fminf(py2,qy2) - fmaxf(py1,qy1), 0.f);
    float inter = iw * ih;
    float uni = pw*ph + gw*gh - inter + eps;
    float iou = inter / uni;
    float cw = fmaxf(px2,qx2) - fminf(px1,qx1);
    float ch = fmaxf(py2,qy2) - fminf(py1,qy1);
    float ca = cw*ch + eps;
    return iou - (ca - uni) / ca;
}

__global__ __launch_bounds__(256) void k_main(
        const float* __restrict__ p0, const float* __restrict__ p1,
        const float* __restrict__ p2, const float* __restrict__ tg,
        float* __restrict__ out)
{
    const int tid  = threadIdx.x;
    const int lane = tid & 31;
    const int wib  = tid >> 5;

    if (blockIdx.x < OBJ_BLOCKS){
        // ================= dense objectness softplus sum =================
        // warps are level-homogeneous (boundaries at g = 153600, 192000)
        int g = blockIdx.x * 256 + tid;
        float s = 0.f;
        int lev = 2;
        if (g < OBJ_GROUPS){
            int cell = g * 4;
            int base, HW;
            const float* P;
            if (cell < CELLS0){ lev = 0; base = cell;               HW = 6400; P = p0; }
            else if (cell < CELLS0 + CELLS1){ lev = 1; base = cell - CELLS0; HW = 1600; P = p1; }
            else { lev = 2; base = cell - (CELLS0 + CELLS1); HW = 400; P = p2; }
            int n_a = base / HW, hw = base - n_a * HW;
            int n = n_a / 3, a = n_a - n * 3;
            const float4 v = *reinterpret_cast<const float4*>(
                P + (size_t)(n*255 + a*85 + 4) * HW + hw);
            s = sp_(v.x) + sp_(v.y) + sp_(v.z) + sp_(v.w);
        }
        #pragma unroll
        for (int d = 16; d; d >>= 1) s += __shfl_xor_sync(0xffffffffu, s, d);
        __shared__ float sh[8];
        if (lane == 0) sh[wib] = s;
        __syncthreads();
        if (tid == 0){
            float t = sh[0]+sh[1]+sh[2]+sh[3]+sh[4]+sh[5]+sh[6]+sh[7];
            atomicAdd(&g_acc[6 + lev], (double)t);
        }
    } else {
        // ============ candidate path: warp per candidate (off-major) ======
        // cid -> (lev, off, a, m): m varies fastest so flagged warps spread
        // evenly across blocks/SMs (even per-SM gather load).
        int cid = ((blockIdx.x - OBJ_BLOCKS) * 256 + tid) >> 5;
        int lev = cid / CPL;
        int k   = cid - lev * CPL;
        int off = k / (NA * MT);
        int r   = k - off * (NA * MT);
        int a   = r / MT;
        int m   = r - a * MT;

        const int W  = (lev==0) ? 80 : ((lev==1) ? 40 : 20);
        const int HW = W * W;
        const float fW = (float)W;

        float t0 = tg[m*6+0];
        float t1 = tg[m*6+1];
        float tx = tg[m*6+2] * fW;
        float ty = tg[m*6+3] * fW;
        float tw = tg[m*6+4] * fW;
        float th = tg[m*6+5] * fW;

        float aw = c_anch[lev][a][0];
        float ah = c_anch[lev][a][1];
        float rw = aw / tw, rh = ah / th;
        float mr = fmaxf(fmaxf(rw, 1.f/rw), fmaxf(rh, 1.f/rh));
        bool bm = mr < 4.0f;

        float fx = tx - floorf(tx);
        float fy = ty - floorf(ty);
        float ox = 0.f, oy = 0.f;
        bool flag = bm;
        if      (off == 1){ flag = bm && (fx < 0.5f) && (tx > 1.0f);       ox =  0.5f; }
        else if (off == 2){ flag = bm && (fy < 0.5f) && (ty > 1.0f);       oy =  0.5f; }
        else if (off == 3){ flag = bm && (fx > 0.5f) && (tx < fW - 1.0f);  ox = -0.5f; }
        else if (off == 4){ flag = bm && (fy > 0.5f) && (ty < fW - 1.0f);  oy = -0.5f; }

        float lbox_c = 0.f, cls_c = 0.f, corr_c = 0.f;
        int cnt_c = 0, cell_c = -1;

        if (flag){   // warp-uniform
            int gx = (int)floorf(tx - ox);
            int gy = (int)floorf(ty - oy);
            float gox = tx - (float)gx;     // unclamped grid (matches reference)
            float goy = ty - (float)gy;
            int gxc = min(max(gx, 0), W-1);
            int gyc = min(max(gy, 0), W-1);
            int img = min(max((int)t0, 0), NIMG-1);
            int cls = (int)t1;

            const float* P = (lev==0) ? p0 : ((lev==1) ? p1 : p2);
            const float* base = P + (size_t)(img*255 + a*85) * HW + gyc * W + gxc;

            // class logits: lane covers c = lane, lane+32, lane+64
            float s = 0.f, picked = 0.f;
            #pragma unroll
            for (int c = lane; c < NCLS; c += 32){
                float v = __ldg(base + (size_t)(5 + c) * HW);
                s += sp_(v);
                if (c == cls) picked = v;
            }
            // box logits (ch 0..3) + obj logit (ch 4) on lanes 0..4
            float opv = 0.f;
            if (lane < 5) opv = __ldg(base + (size_t)lane * HW);

            #pragma unroll
            for (int d = 16; d; d >>= 1){
                s      += __shfl_xor_sync(0xffffffffu, s, d);
                picked += __shfl_xor_sync(0xffffffffu, picked, d);
            }
            float op0 = __shfl_sync(0xffffffffu, opv, 0);
            float op1 = __shfl_sync(0xffffffffu, opv, 1);
            float op2 = __shfl_sync(0xffffffffu, opv, 2);
            float op3 = __shfl_sync(0xffffffffu, opv, 3);
            float xob = __shfl_sync(0xffffffffu, opv, 4);

            if (lane == 0){
                float px = sig_(op0) * 2.f - 0.5f;
                float py = sig_(op1) * 2.f - 0.5f;
                float sw = sig_(op2) * 2.f;
                float sh2 = sig_(op3) * 2.f;
                float pw = sw * sw * aw;
                float ph = sh2 * sh2 * ah;
                float gi = giou_(px, py, pw, ph, gox, goy, tw, th);
                lbox_c = 1.f - gi;
                cls_c  = s - picked;       // sum_c softplus(x_c) - x_cls
                cnt_c  = 1;
                float ov = fmaxf(gi, 0.f);
                if (ov > 0.f){
                    int lvoff = (lev==0) ? 0 : ((lev==1) ? CELLS0 : (CELLS0+CELLS1));
                    int cell = lvoff + (img*3 + a) * HW + gyc * W + gxc;
                    unsigned old = atomicMax(&g_objmax[cell], __float_as_uint(ov));
                    float oldf = __uint_as_float(old);
                    if (ov > oldf){
                        // telescoping: sum of successful raises == final max
                        // (x identical per cell); serialized by L2 RMW, no
                        // fence needed — g_objmax is never re-read.
                        corr_c = (ov - oldf) * xob;
                        if (old == 0u) cell_c = cell;   // first raiser lists cell
                    }
                }
            }
        }

        // ---- block reduction (blocks are level-homogeneous) ----
        __shared__ float sh_lb[8], sh_lc[8], sh_co[8];
        __shared__ int   sh_cn[8], sh_cell[8];
        if (lane == 0){
            sh_lb[wib] = lbox_c; sh_lc[wib] = cls_c; sh_co[wib] = corr_c;
            sh_cn[wib] = cnt_c;  sh_cell[wib] = cell_c;
        }
        __syncthreads();
        if (tid == 0){
            float lb = 0.f, lc = 0.f, co = 0.f; int cn = 0, nv = 0;
            int cells[8];
            #pragma unroll
            for (int i = 0; i < 8; i++){
                lb += sh_lb[i]; lc += sh_lc[i]; co += sh_co[i]; cn += sh_cn[i];
                if (sh_cell[i] >= 0) cells[nv++] = sh_cell[i];
            }
            if (cn){
                atomicAdd(&g_acc[lev],     (double)lb);
                atomicAdd(&g_acc[3 + lev], (double)lc);
                atomicAdd(&g_cnt[lev], cn);
            }
            if (co != 0.f) atomicAdd(&g_acc[9 + lev], (double)co);
            if (nv){
                int bse = atomicAdd(&g_nflag, nv);
                for (int i = 0; i < nv; i++) g_cellList[bse + i] = cells[i];
            }
        }
    }

    // ================= common epilogue: last block finalizes ==============
    __shared__ int s_last, s_n;
    __syncthreads();
    if (tid == 0){
        __threadfence();   // publish this block's g_cellList / g_acc writes
        s_last = (atomicAdd(&g_done, 1) == GRID - 1) ? 1 : 0;
        if (s_last) s_n = g_nflag;
    }
    __syncthreads();
    if (s_last){
        // zero every touched g_objmax cell (list-driven, independent stores)
        int n = s_n;
        for (int i = tid; i < n; i += 256) g_objmax[g_cellList[i]] = 0u;

        if (tid == 0){
            const double cells[3] = {614400.0, 153600.0, 38400.0};
            const double bal[3]   = {4.0, 1.0, 0.4};
            double lbox = 0.0, lcls = 0.0, lobj = 0.0;
            #pragma unroll
            for (int l = 0; l < 3; l++){
                double cnt = (g_cnt[l] > 0) ? (double)g_cnt[l] : 1.0;
                lbox += g_acc[l] / cnt;
                lcls += g_acc[3 + l] / (cnt * (double)NCLS);
                lobj += ((g_acc[6 + l] - g_acc[9 + l]) / cells[l]) * bal[l];
            }
            out[0] = (float)((0.05 * lbox + 0.5 * lcls + lobj) * 32.0);
            // reset all state for next graph replay
            #pragma unroll
            for (int j = 0; j < 12; j++) g_acc[j] = 0.0;
            g_cnt[0] = g_cnt[1] = g_cnt[2] = 0;
            g_nflag = 0;
            g_done  = 0;
        }
    }
}

// ---------------------------------------------------------------------------
extern "C" void kernel_launch(void* const* d_in, const int* in_sizes, int n_in,
                              void* d_out, int out_size){
    const float* p0 = (const float*)d_in[0];
    const float* p1 = (const float*)d_in[1];
    const float* p2 = (const float*)d_in[2];
    const float* tg = (const float*)d_in[3];
    float* out = (float*)d_out;
    (void)in_sizes; (void)n_in; (void)out_size;

    k_main<<<GRID, 256>>>(p0, p1, p2, tg, out);
}

// round 8
// speedup vs baseline: 1.3526x; 1.3526x over previous
#include <cuda_runtime.h>

// ---------------------------------------------------------------------------
// ComputeLoss (YOLOv5-style), fixed shapes:
//   p0: (32,255,80,80)  p1: (32,255,40,40)  p2: (32,255,20,20)
//   targets: (1024,6) = [img, cls, cx, cy, w, h]
// Output: one float32 scalar.
//
// Kernel A (hot): dense softplus(obj) stream + warp-per-candidate gathers.
//   NO epilogue, NO fences — kernel boundary provides all ordering.
//   Telescoping atomicMax: each successful raise contributes (new-old)*x to
//   the obj correction, so the per-cell max is never re-read anywhere.
// Kernel B (1 block): zero the listed g_objmax cells, finalize scalar, reset.
// ---------------------------------------------------------------------------

#define NIMG 32
#define NA   3
#define NCLS 80
#define MT   1024
#define CPL  (5*NA*MT)            // 15360 candidates per level
#define TOTC (3*CPL)              // 46080
#define CELLS0 (NIMG*NA*80*80)    // 614400
#define CELLS1 (NIMG*NA*40*40)    // 153600
#define CELLS2 (NIMG*NA*20*20)    // 38400
#define CELLS_TOT (CELLS0+CELLS1+CELLS2)   // 806400

#define OBJ_GROUPS (CELLS_TOT/4)              // 201600 float4 groups
#define OBJ_BLOCKS ((OBJ_GROUPS + 255)/256)   // 788
#define CAND_BLOCKS (TOTC/8)                  // 5760
#define GRID (OBJ_BLOCKS + CAND_BLOCKS)       // 6548

__constant__ float c_anch[3][3][2] = {
  {{1.25f,1.625f},{2.0f,3.75f},{4.125f,2.875f}},
  {{1.875f,3.8125f},{3.875f,2.8125f},{3.6875f,7.4375f}},
  {{3.625f,2.8125f},{4.875f,6.1875f},{11.65625f,10.1875f}}
};

// per-cell objectness max (float bits >= 0). Zero at module load; kernel B
// zeroes every touched cell each launch (list-driven).
__device__ unsigned g_objmax[CELLS_TOT];
__device__ int   g_cellList[TOTC];
__device__ int   g_nflag;
// [0..2]=lbox, [3..5]=cls, [6..8]=obj_softplus, [9..11]=obj_corr
__device__ double g_acc[12];
__device__ int g_cnt[3];

__device__ __forceinline__ float sp_(float x){          // softplus (fast-math)
    return fmaxf(x, 0.f) + __logf(1.f + __expf(-fabsf(x)));
}
__device__ __forceinline__ float sig_(float x){
    return 1.f / (1.f + __expf(-x));
}

__device__ __forceinline__ float giou_(float px,float py,float pw,float ph,
                                       float gx,float gy,float gw,float gh){
    const float eps = 1e-7f;
    float px1 = px - pw*0.5f, py1 = py - ph*0.5f;
    float px2 = px + pw*0.5f, py2 = py + ph*0.5f;
    float qx1 = gx - gw*0.5f, qy1 = gy - gh*0.5f;
    float qx2 = gx + gw*0.5f, qy2 = gy + gh*0.5f;
    float iw = fmaxf(fminf(px2,qx2) - fmaxf(px1,qx1), 0.f);
    float ih = fmaxf(fminf(py2,qy2) - fmaxf(py1,qy1), 0.f);
    float inter = iw * ih;
    float uni = pw*ph + gw*gh - inter + eps;
    float iou = inter / uni;
    float cw = fmaxf(px2,qx2) - fminf(px1,qx1);
    float ch = fmaxf(py2,qy2) - fminf(py1,qy1);
    float ca = cw*ch + eps;
    return iou - (ca - uni) / ca;
}

// ============================ Kernel A ======================================
__global__ __launch_bounds__(256) void k_main(
        const float* __restrict__ p0, const float* __restrict__ p1,
        const float* __restrict__ p2, const float* __restrict__ tg)
{
    const int tid  = threadIdx.x;
    const int lane = tid & 31;
    const int wib  = tid >> 5;

    if (blockIdx.x < OBJ_BLOCKS){
        // ---------------- dense objectness softplus sum -------------------
        // warps are level-homogeneous (boundaries at g = 153600, 192000)
        int g = blockIdx.x * 256 + tid;
        float s = 0.f;
        int lev = 2;
        if (g < OBJ_GROUPS){
            int cell = g * 4;
            int base, HW;
            const float* P;
            if (cell < CELLS0){ lev = 0; base = cell;               HW = 6400; P = p0; }
            else if (cell < CELLS0 + CELLS1){ lev = 1; base = cell - CELLS0; HW = 1600; P = p1; }
            else { lev = 2; base = cell - (CELLS0 + CELLS1); HW = 400; P = p2; }
            int n_a = base / HW, hw = base - n_a * HW;
            int n = n_a / 3, a = n_a - n * 3;
            const float4 v = *reinterpret_cast<const float4*>(
                P + (size_t)(n*255 + a*85 + 4) * HW + hw);
            s = sp_(v.x) + sp_(v.y) + sp_(v.z) + sp_(v.w);
        }
        #pragma unroll
        for (int d = 16; d; d >>= 1) s += __shfl_xor_sync(0xffffffffu, s, d);
        __shared__ float sh[8];
        if (lane == 0) sh[wib] = s;
        __syncthreads();
        if (tid == 0){
            float t = sh[0]+sh[1]+sh[2]+sh[3]+sh[4]+sh[5]+sh[6]+sh[7];
            atomicAdd(&g_acc[6 + lev], (double)t);
        }
        return;
    }

    // ---------- candidate path: warp per candidate (off-major) ------------
    // cid -> (lev, off, a, m): m fastest => flagged warps spread evenly.
    int cid = ((blockIdx.x - OBJ_BLOCKS) * 256 + tid) >> 5;
    int lev = cid / CPL;
    int k   = cid - lev * CPL;
    int off = k / (NA * MT);
    int r   = k - off * (NA * MT);
    int a   = r / MT;
    int m   = r - a * MT;

    const int W  = (lev==0) ? 80 : ((lev==1) ? 40 : 20);
    const int HW = W * W;
    const float fW = (float)W;

    float t0 = tg[m*6+0];
    float t1 = tg[m*6+1];
    float tx = tg[m*6+2] * fW;
    float ty = tg[m*6+3] * fW;
    float tw = tg[m*6+4] * fW;
    float th = tg[m*6+5] * fW;

    float aw = c_anch[lev][a][0];
    float ah = c_anch[lev][a][1];
    float rw = aw / tw, rh = ah / th;
    float mr = fmaxf(fmaxf(rw, 1.f/rw), fmaxf(rh, 1.f/rh));
    bool bm = mr < 4.0f;

    float fx = tx - floorf(tx);
    float fy = ty - floorf(ty);
    float ox = 0.f, oy = 0.f;
    bool flag = bm;
    if      (off == 1){ flag = bm && (fx < 0.5f) && (tx > 1.0f);       ox =  0.5f; }
    else if (off == 2){ flag = bm && (fy < 0.5f) && (ty > 1.0f);       oy =  0.5f; }
    else if (off == 3){ flag = bm && (fx > 0.5f) && (tx < fW - 1.0f);  ox = -0.5f; }
    else if (off == 4){ flag = bm && (fy > 0.5f) && (ty < fW - 1.0f);  oy = -0.5f; }

    float lbox_c = 0.f, cls_c = 0.f, corr_c = 0.f;
    int cnt_c = 0, cell_c = -1;

    if (flag){   // warp-uniform
        int gx = (int)floorf(tx - ox);
        int gy = (int)floorf(ty - oy);
        float gox = tx - (float)gx;     // unclamped grid (matches reference)
        float goy = ty - (float)gy;
        int gxc = min(max(gx, 0), W-1);
        int gyc = min(max(gy, 0), W-1);
        int img = min(max((int)t0, 0), NIMG-1);
        int cls = (int)t1;

        const float* P = (lev==0) ? p0 : ((lev==1) ? p1 : p2);
        const float* base = P + (size_t)(img*255 + a*85) * HW + gyc * W + gxc;

        // class logits: lane covers c = lane, lane+32, lane+64
        float s = 0.f, picked = 0.f;
        #pragma unroll
        for (int c = lane; c < NCLS; c += 32){
            float v = __ldg(base + (size_t)(5 + c) * HW);
            s += sp_(v);
            if (c == cls) picked = v;
        }
        // box logits (ch 0..3) + obj logit (ch 4) on lanes 0..4
        float opv = 0.f;
        if (lane < 5) opv = __ldg(base + (size_t)lane * HW);

        #pragma unroll
        for (int d = 16; d; d >>= 1){
            s      += __shfl_xor_sync(0xffffffffu, s, d);
            picked += __shfl_xor_sync(0xffffffffu, picked, d);
        }
        float op0 = __shfl_sync(0xffffffffu, opv, 0);
        float op1 = __shfl_sync(0xffffffffu, opv, 1);
        float op2 = __shfl_sync(0xffffffffu, opv, 2);
        float op3 = __shfl_sync(0xffffffffu, opv, 3);
        float xob = __shfl_sync(0xffffffffu, opv, 4);

        if (lane == 0){
            float px = sig_(op0) * 2.f - 0.5f;
            float py = sig_(op1) * 2.f - 0.5f;
            float sw = sig_(op2) * 2.f;
            float sh2 = sig_(op3) * 2.f;
            float pw = sw * sw * aw;
            float ph = sh2 * sh2 * ah;
            float gi = giou_(px, py, pw, ph, gox, goy, tw, th);
            lbox_c = 1.f - gi;
            cls_c  = s - picked;       // sum_c softplus(x_c) - x_cls
            cnt_c  = 1;
            float ov = fmaxf(gi, 0.f);
            if (ov > 0.f){
                int lvoff = (lev==0) ? 0 : ((lev==1) ? CELLS0 : (CELLS0+CELLS1));
                int cell = lvoff + (img*3 + a) * HW + gyc * W + gxc;
                unsigned old = atomicMax(&g_objmax[cell], __float_as_uint(ov));
                float oldf = __uint_as_float(old);
                if (ov > oldf){
                    corr_c = (ov - oldf) * xob;     // telescopes to max*x
                    if (old == 0u) cell_c = cell;   // first raiser lists cell
                }
            }
        }
    }

    // ---- block reduction (blocks are level-homogeneous) ----
    __shared__ float sh_lb[8], sh_lc[8], sh_co[8];
    __shared__ int   sh_cn[8], sh_cell[8];
    if (lane == 0){
        sh_lb[wib] = lbox_c; sh_lc[wib] = cls_c; sh_co[wib] = corr_c;
        sh_cn[wib] = cnt_c;  sh_cell[wib] = cell_c;
    }
    __syncthreads();
    if (tid == 0){
        float lb = 0.f, lc = 0.f, co = 0.f; int cn = 0, nv = 0;
        int cells[8];
        #pragma unroll
        for (int i = 0; i < 8; i++){
            lb += sh_lb[i]; lc += sh_lc[i]; co += sh_co[i]; cn += sh_cn[i];
            if (sh_cell[i] >= 0) cells[nv++] = sh_cell[i];
        }
        if (cn){
            atomicAdd(&g_acc[lev],     (double)lb);
            atomicAdd(&g_acc[3 + lev], (double)lc);
            atomicAdd(&g_cnt[lev], cn);
        }
        if (co != 0.f) atomicAdd(&g_acc[9 + lev], (double)co);
        if (nv){
            int bse = atomicAdd(&g_nflag, nv);
            for (int i = 0; i < nv; i++) g_cellList[bse + i] = cells[i];
        }
    }
}

// ============================ Kernel B ======================================
// Single block: zero listed cells, finalize scalar, reset all state.
// Kernel boundary guarantees visibility of kernel A's writes.
__global__ __launch_bounds__(1024) void k_tail(float* __restrict__ out)
{
    const int tid = threadIdx.x;
    int n = min(g_nflag, TOTC);  // every thread reads BEFORE the reset below
    __syncthreads();

    for (int i = tid; i < n; i += 1024) g_objmax[g_cellList[i]] = 0u;

    if (tid == 0){
        const double cells[3] = {614400.0, 153600.0, 38400.0};
        const double bal[3]   = {4.0, 1.0, 0.4};
        double lbox = 0.0, lcls = 0.0, lobj = 0.0;
        #pragma unroll
        for (int l = 0; l < 3; l++){
            double cnt = (g_cnt[l] > 0) ? (double)g_cnt[l] : 1.0;
            lbox += g_acc[l] / cnt;
            lcls += g_acc[3 + l] / (cnt * (double)NCLS);
            lobj += ((g_acc[6 + l] - g_acc[9 + l]) / cells[l]) * bal[l];
        }
        out[0] = (float)((0.05 * lbox + 0.5 * lcls + lobj) * 32.0);
        // reset state for next graph replay
        #pragma unroll
        for (int j = 0; j < 12; j++) g_acc[j] = 0.0;
        g_cnt[0] = g_cnt[1] = g_cnt[2] = 0;
        g_nflag = 0;
    }
}

// ---------------------------------------------------------------------------
extern "C" void kernel_launch(void* const* d_in, const int* in_sizes, int n_in,
                              void* d_out, int out_size){
    const float* p0 = (const float*)d_in[0];
    const float* p1 = (const float*)d_in[1];
    const float* p2 = (const float*)d_in[2];
    const float* tg = (const float*)d_in[3];
    float* out = (float*)d_out;
    (void)in_sizes; (void)n_in; (void)out_size;

    k_main<<<GRID, 256>>>(p0, p1, p2, tg);
    k_tail<<<1, 1024>>>(out);
}

// round 9
// speedup vs baseline: 1.5704x; 1.1610x over previous
#include <cuda_runtime.h>

// ---------------------------------------------------------------------------
// ComputeLoss (YOLOv5-style), fixed shapes:
//   p0: (32,255,80,80)  p1: (32,255,40,40)  p2: (32,255,20,20)
//   targets: (1024,6) = [img, cls, cx, cy, w, h]
// Output: one float32 scalar.
//
// 3 launches:
//   k_main : dense softplus(obj) stream + warp-per-candidate gathers.
//            Telescoping atomicMax => per-cell max never re-read. No fences.
//   k_zero : 64 blocks zero the listed g_objmax cells (parallel, latency-flat)
//   k_fin  : 1 warp — finalize scalar, reset all state (after k_zero's
//            readers of g_nflag are done, by kernel boundary).
// ---------------------------------------------------------------------------

#define NIMG 32
#define NA   3
#define NCLS 80
#define MT   1024
#define CPL  (5*NA*MT)            // 15360 candidates per level
#define TOTC (3*CPL)              // 46080
#define CELLS0 (NIMG*NA*80*80)    // 614400
#define CELLS1 (NIMG*NA*40*40)    // 153600
#define CELLS2 (NIMG*NA*20*20)    // 38400
#define CELLS_TOT (CELLS0+CELLS1+CELLS2)   // 806400

#define OBJ_GROUPS (CELLS_TOT/4)              // 201600 float4 groups
#define OBJ_BLOCKS ((OBJ_GROUPS + 255)/256)   // 788
#define CAND_BLOCKS (TOTC/8)                  // 5760
#define GRID (OBJ_BLOCKS + CAND_BLOCKS)       // 6548

__constant__ float c_anch[3][3][2] = {
  {{1.25f,1.625f},{2.0f,3.75f},{4.125f,2.875f}},
  {{1.875f,3.8125f},{3.875f,2.8125f},{3.6875f,7.4375f}},
  {{3.625f,2.8125f},{4.875f,6.1875f},{11.65625f,10.1875f}}
};

// per-cell objectness max (float bits >= 0). Zero at module load; k_zero
// zeroes every touched cell each launch (list-driven).
__device__ unsigned g_objmax[CELLS_TOT];
__device__ int   g_cellList[TOTC];
__device__ int   g_nflag;
// [0..2]=lbox, [3..5]=cls, [6..8]=obj_softplus, [9..11]=obj_corr
__device__ double g_acc[12];
__device__ int g_cnt[3];

__device__ __forceinline__ float sp_(float x){          // softplus (fast-math)
    return fmaxf(x, 0.f) + __logf(1.f + __expf(-fabsf(x)));
}
__device__ __forceinline__ float sig_(float x){
    return 1.f / (1.f + __expf(-x));
}

__device__ __forceinline__ float giou_(float px,float py,float pw,float ph,
                                       float gx,float gy,float gw,float gh){
    const float eps = 1e-7f;
    float px1 = px - pw*0.5f, py1 = py - ph*0.5f;
    float px2 = px + pw*0.5f, py2 = py + ph*0.5f;
    float qx1 = gx - gw*0.5f, qy1 = gy - gh*0.5f;
    float qx2 = gx + gw*0.5f, qy2 = gy + gh*0.5f;
    float iw = fmaxf(fminf(px2,qx2) - fmaxf(px1,qx1), 0.f);
    float ih = fmaxf(fminf(py2,qy2) - fmaxf(py1,qy1), 0.f);
    float inter = iw * ih;
    float uni = pw*ph + gw*gh - inter + eps;
    float iou = inter / uni;
    float cw = fmaxf(px2,qx2) - fminf(px1,qx1);
    float ch = fmaxf(py2,qy2) - fminf(py1,qy1);
    float ca = cw*ch + eps;
    return iou - (ca - uni) / ca;
}

// ============================ Kernel A ======================================
__global__ __launch_bounds__(256) void k_main(
        const float* __restrict__ p0, const float* __restrict__ p1,
        const float* __restrict__ p2, const float* __restrict__ tg)
{
    const int tid  = threadIdx.x;
    const int lane = tid & 31;
    const int wib  = tid >> 5;

    if (blockIdx.x < OBJ_BLOCKS){
        // ---------------- dense objectness softplus sum -------------------
        // warps are level-homogeneous (boundaries at g = 153600, 192000)
        int g = blockIdx.x * 256 + tid;
        float s = 0.f;
        int lev = 2;
        if (g < OBJ_GROUPS){
            int cell = g * 4;
            int base, HW;
            const float* P;
            if (cell < CELLS0){ lev = 0; base = cell;               HW = 6400; P = p0; }
            else if (cell < CELLS0 + CELLS1){ lev = 1; base = cell - CELLS0; HW = 1600; P = p1; }
            else { lev = 2; base = cell - (CELLS0 + CELLS1); HW = 400; P = p2; }
            int n_a = base / HW, hw = base - n_a * HW;
            int n = n_a / 3, a = n_a - n * 3;
            const float4 v = *reinterpret_cast<const float4*>(
                P + (size_t)(n*255 + a*85 + 4) * HW + hw);
            s = sp_(v.x) + sp_(v.y) + sp_(v.z) + sp_(v.w);
        }
        #pragma unroll
        for (int d = 16; d; d >>= 1) s += __shfl_xor_sync(0xffffffffu, s, d);
        __shared__ float sh[8];
        if (lane == 0) sh[wib] = s;
        __syncthreads();
        if (tid == 0){
            float t = sh[0]+sh[1]+sh[2]+sh[3]+sh[4]+sh[5]+sh[6]+sh[7];
            atomicAdd(&g_acc[6 + lev], (double)t);
        }
        return;
    }

    // ---------- candidate path: warp per candidate (off-major) ------------
    // cid -> (lev, off, a, m): m fastest => flagged warps spread evenly.
    int cid = ((blockIdx.x - OBJ_BLOCKS) * 256 + tid) >> 5;
    int lev = cid / CPL;
    int k   = cid - lev * CPL;
    int off = k / (NA * MT);
    int r   = k - off * (NA * MT);
    int a   = r / MT;
    int m   = r - a * MT;

    const int W  = (lev==0) ? 80 : ((lev==1) ? 40 : 20);
    const int HW = W * W;
    const float fW = (float)W;

    float t0 = tg[m*6+0];
    float t1 = tg[m*6+1];
    float tx = tg[m*6+2] * fW;
    float ty = tg[m*6+3] * fW;
    float tw = tg[m*6+4] * fW;
    float th = tg[m*6+5] * fW;

    float aw = c_anch[lev][a][0];
    float ah = c_anch[lev][a][1];
    float rw = aw / tw, rh = ah / th;
    float mr = fmaxf(fmaxf(rw, 1.f/rw), fmaxf(rh, 1.f/rh));
    bool bm = mr < 4.0f;

    float fx = tx - floorf(tx);
    float fy = ty - floorf(ty);
    float ox = 0.f, oy = 0.f;
    bool flag = bm;
    if      (off == 1){ flag = bm && (fx < 0.5f) && (tx > 1.0f);       ox =  0.5f; }
    else if (off == 2){ flag = bm && (fy < 0.5f) && (ty > 1.0f);       oy =  0.5f; }
    else if (off == 3){ flag = bm && (fx > 0.5f) && (tx < fW - 1.0f);  ox = -0.5f; }
    else if (off == 4){ flag = bm && (fy > 0.5f) && (ty < fW - 1.0f);  oy = -0.5f; }

    float lbox_c = 0.f, cls_c = 0.f, corr_c = 0.f;
    int cnt_c = 0, cell_c = -1;

    if (flag){   // warp-uniform
        int gx = (int)floorf(tx - ox);
        int gy = (int)floorf(ty - oy);
        float gox = tx - (float)gx;     // unclamped grid (matches reference)
        float goy = ty - (float)gy;
        int gxc = min(max(gx, 0), W-1);
        int gyc = min(max(gy, 0), W-1);
        int img = min(max((int)t0, 0), NIMG-1);
        int cls = (int)t1;

        const float* P = (lev==0) ? p0 : ((lev==1) ? p1 : p2);
        const float* base = P + (size_t)(img*255 + a*85) * HW + gyc * W + gxc;

        // class logits: lane covers c = lane, lane+32, lane+64
        float s = 0.f, picked = 0.f;
        #pragma unroll
        for (int c = lane; c < NCLS; c += 32){
            float v = __ldg(base + (size_t)(5 + c) * HW);
            s += sp_(v);
            if (c == cls) picked = v;
        }
        // box logits (ch 0..3) + obj logit (ch 4) on lanes 0..4
        float opv = 0.f;
        if (lane < 5) opv = __ldg(base + (size_t)lane * HW);

        #pragma unroll
        for (int d = 16; d; d >>= 1){
            s      += __shfl_xor_sync(0xffffffffu, s, d);
            picked += __shfl_xor_sync(0xffffffffu, picked, d);
        }
        float op0 = __shfl_sync(0xffffffffu, opv, 0);
        float op1 = __shfl_sync(0xffffffffu, opv, 1);
        float op2 = __shfl_sync(0xffffffffu, opv, 2);
        float op3 = __shfl_sync(0xffffffffu, opv, 3);
        float xob = __shfl_sync(0xffffffffu, opv, 4);

        if (lane == 0){
            float px = sig_(op0) * 2.f - 0.5f;
            float py = sig_(op1) * 2.f - 0.5f;
            float sw = sig_(op2) * 2.f;
            float sh2 = sig_(op3) * 2.f;
            float pw = sw * sw * aw;
            float ph = sh2 * sh2 * ah;
            float gi = giou_(px, py, pw, ph, gox, goy, tw, th);
            lbox_c = 1.f - gi;
            cls_c  = s - picked;       // sum_c softplus(x_c) - x_cls
            cnt_c  = 1;
            float ov = fmaxf(gi, 0.f);
            if (ov > 0.f){
                int lvoff = (lev==0) ? 0 : ((lev==1) ? CELLS0 : (CELLS0+CELLS1));
                int cell = lvoff + (img*3 + a) * HW + gyc * W + gxc;
                unsigned old = atomicMax(&g_objmax[cell], __float_as_uint(ov));
                float oldf = __uint_as_float(old);
                if (ov > oldf){
                    corr_c = (ov - oldf) * xob;     // telescopes to max*x
                    if (old == 0u) cell_c = cell;   // first raiser lists cell
                }
            }
        }
    }

    // ---- block reduction (blocks are level-homogeneous) ----
    __shared__ float sh_lb[8], sh_lc[8], sh_co[8];
    __shared__ int   sh_cn[8], sh_cell[8];
    if (lane == 0){
        sh_lb[wib] = lbox_c; sh_lc[wib] = cls_c; sh_co[wib] = corr_c;
        sh_cn[wib] = cnt_c;  sh_cell[wib] = cell_c;
    }
    __syncthreads();
    if (tid == 0){
        float lb = 0.f, lc = 0.f, co = 0.f; int cn = 0, nv = 0;
        int cells[8];
        #pragma unroll
        for (int i = 0; i < 8; i++){
            lb += sh_lb[i]; lc += sh_lc[i]; co += sh_co[i]; cn += sh_cn[i];
            if (sh_cell[i] >= 0) cells[nv++] = sh_cell[i];
        }
        if (cn){
            atomicAdd(&g_acc[lev],     (double)lb);
            atomicAdd(&g_acc[3 + lev], (double)lc);
            atomicAdd(&g_cnt[lev], cn);
        }
        if (co != 0.f) atomicAdd(&g_acc[9 + lev], (double)co);
        if (nv){
            int bse = atomicAdd(&g_nflag, nv);
            for (int i = 0; i < nv; i++) g_cellList[bse + i] = cells[i];
        }
    }
}

// ============================ Kernel B ======================================
// 64 blocks: zero the listed g_objmax cells. g_nflag is read-only here.
__global__ __launch_bounds__(256) void k_zero()
{
    int n = min(g_nflag, TOTC);
    for (int i = blockIdx.x * 256 + threadIdx.x; i < n; i += 64 * 256)
        g_objmax[g_cellList[i]] = 0u;
}

// ============================ Kernel C ======================================
// 1 warp: finalize scalar and reset all state (strictly after k_zero).
__global__ void k_fin(float* __restrict__ out)
{
    const int tid = threadIdx.x;
    if (tid == 0){
        const double cells[3] = {614400.0, 153600.0, 38400.0};
        const double bal[3]   = {4.0, 1.0, 0.4};
        double lbox = 0.0, lcls = 0.0, lobj = 0.0;
        #pragma unroll
        for (int l = 0; l < 3; l++){
            double cnt = (g_cnt[l] > 0) ? (double)g_cnt[l] : 1.0;
            lbox += g_acc[l] / cnt;
            lcls += g_acc[3 + l] / (cnt * (double)NCLS);
            lobj += ((g_acc[6 + l] - g_acc[9 + l]) / cells[l]) * bal[l];
        }
        out[0] = (float)((0.05 * lbox + 0.5 * lcls + lobj) * 32.0);
    }
    // reset state for next graph replay (lanes share the tiny work)
    if (tid < 12) g_acc[tid] = 0.0;
    if (tid >= 12 && tid < 15) g_cnt[tid - 12] = 0;
    if (tid == 15) g_nflag = 0;
}

// ---------------------------------------------------------------------------
extern "C" void kernel_launch(void* const* d_in, const int* in_sizes, int n_in,
                              void* d_out, int out_size){
    const float* p0 = (const float*)d_in[0];
    const float* p1 = (const float*)d_in[1];
    const float* p2 = (const float*)d_in[2];
    const float* tg = (const float*)d_in[3];
    float* out = (float*)d_out;
    (void)in_sizes; (void)n_in; (void)out_size;

    k_main<<<GRID, 256>>>(p0, p1, p2, tg);
    k_zero<<<64, 256>>>();
    k_fin <<<1, 32>>>(out);
}

// round 12
// speedup vs baseline: 1.7350x; 1.1048x over previous
#include <cuda_runtime.h>

// ---------------------------------------------------------------------------
// ComputeLoss (YOLOv5-style), fixed shapes:
//   p0: (32,255,80,80)  p1: (32,255,40,40)  p2: (32,255,20,20)
//   targets: (1024,6) = [img, cls, cx, cy, w, h]
// Output: one float32 scalar.
//
// 3 launches:
//   k_main : dense softplus(obj) stream + ONE WARP PER (lev,m,a) GROUP that
//            handles all <=3 flagged offset-candidates (center, x-, y-)
//            together. All warp shuffles execute warp-wide (convergent);
//            only scalar work lives in the lane==0 region.
//   k_zero : 64 blocks zero the listed g_objmax cells
//   k_fin  : finalize scalar, reset state.
// ---------------------------------------------------------------------------

#define NIMG 32
#define NA   3
#define NCLS 80
#define MT   1024
#define CELLS0 (NIMG*NA*80*80)    // 614400
#define CELLS1 (NIMG*NA*40*40)    // 153600
#define CELLS2 (NIMG*NA*20*20)    // 38400
#define CELLS_TOT (CELLS0+CELLS1+CELLS2)   // 806400
#define TOTCELLS (3*3*MT*3)       // list capacity: 3 cells per group max

#define OBJ_GROUPS (CELLS_TOT/4)              // 201600 float4 groups
#define OBJ_BLOCKS ((OBJ_GROUPS + 255)/256)   // 788
#define NGRP (3*MT*NA)                        // 9216 groups (lev,m,a)
#define CAND_BLOCKS (NGRP/8)                  // 1152
#define GRID (OBJ_BLOCKS + CAND_BLOCKS)       // 1940

__constant__ float c_anch[3][3][2] = {
  {{1.25f,1.625f},{2.0f,3.75f},{4.125f,2.875f}},
  {{1.875f,3.8125f},{3.875f,2.8125f},{3.6875f,7.4375f}},
  {{3.625f,2.8125f},{4.875f,6.1875f},{11.65625f,10.1875f}}
};

// per-cell objectness max (float bits >= 0). Zero at module load; k_zero
// zeroes every touched cell each launch (list-driven).
__device__ unsigned g_objmax[CELLS_TOT];
__device__ int   g_cellList[TOTCELLS];
__device__ int   g_nflag;
// [0..2]=lbox, [3..5]=cls, [6..8]=obj_softplus, [9..11]=obj_corr
__device__ double g_acc[12];
__device__ int g_cnt[3];

__device__ __forceinline__ float sp_(float x){          // softplus (fast-math)
    return fmaxf(x, 0.f) + __logf(1.f + __expf(-fabsf(x)));
}
__device__ __forceinline__ float sig_(float x){
    return 1.f / (1.f + __expf(-x));
}

__device__ __forceinline__ float giou_(float px,float py,float pw,float ph,
                                       float gx,float gy,float gw,float gh){
    const float eps = 1e-7f;
    float px1 = px - pw*0.5f, py1 = py - ph*0.5f;
    float px2 = px + pw*0.5f, py2 = py + ph*0.5f;
    float qx1 = gx - gw*0.5f, qy1 = gy - gh*0.5f;
    float qx2 = gx + gw*0.5f, qy2 = gy + gh*0.5f;
    float iw = fmaxf(fminf(px2,qx2) - fmaxf(px1,qx1), 0.f);
    float ih = fmaxf(fminf(py2,qy2) - fmaxf(py1,qy1), 0.f);
    float inter = iw * ih;
    float uni = pw*ph + gw*gh - inter + eps;
    float iou = inter / uni;
    float cw = fmaxf(px2,qx2) - fminf(px1,qx1);
    float ch = fmaxf(py2,qy2) - fminf(py1,qy1);
    float ca = cw*ch + eps;
    return iou - (ca - uni) / ca;
}

// warp butterfly sum (warp-wide, convergent)
__device__ __forceinline__ float wsum_(float v){
    #pragma unroll
    for (int d = 16; d; d >>= 1) v += __shfl_xor_sync(0xffffffffu, v, d);
    return v;
}

// ============================ Kernel A ======================================
__global__ __launch_bounds__(256) void k_main(
        const float* __restrict__ p0, const float* __restrict__ p1,
        const float* __restrict__ p2, const float* __restrict__ tg)
{
    const int tid  = threadIdx.x;
    const int lane = tid & 31;
    const int wib  = tid >> 5;

    if (blockIdx.x < OBJ_BLOCKS){
        // ---------------- dense objectness softplus sum -------------------
        // warps are level-homogeneous (boundaries at g = 153600, 192000)
        int g = blockIdx.x * 256 + tid;
        float s = 0.f;
        int lev = 2;
        if (g < OBJ_GROUPS){
            int cell = g * 4;
            int base, HW;
            const float* P;
            if (cell < CELLS0){ lev = 0; base = cell;               HW = 6400; P = p0; }
            else if (cell < CELLS0 + CELLS1){ lev = 1; base = cell - CELLS0; HW = 1600; P = p1; }
            else { lev = 2; base = cell - (CELLS0 + CELLS1); HW = 400; P = p2; }
            int n_a = base / HW, hw = base - n_a * HW;
            int n = n_a / 3, a = n_a - n * 3;
            const float4 v = *reinterpret_cast<const float4*>(
                P + (size_t)(n*255 + a*85 + 4) * HW + hw);
            s = sp_(v.x) + sp_(v.y) + sp_(v.z) + sp_(v.w);
        }
        s = wsum_(s);
        __shared__ float sh[8];
        if (lane == 0) sh[wib] = s;
        __syncthreads();
        if (tid == 0){
            float t = sh[0]+sh[1]+sh[2]+sh[3]+sh[4]+sh[5]+sh[6]+sh[7];
            atomicAdd(&g_acc[6 + lev], (double)t);
        }
        return;
    }

    // ---------- candidate path: ONE WARP PER (lev, m, a) GROUP ------------
    int gid = ((blockIdx.x - OBJ_BLOCKS) * 256 + tid) >> 5;   // 0..9215
    int lev = gid / (MT * NA);
    int r   = gid - lev * (MT * NA);
    int m   = r / NA;
    int a   = r - m * NA;

    const int W  = (lev==0) ? 80 : ((lev==1) ? 40 : 20);
    const int HW = W * W;
    const float fW = (float)W;

    float t0 = tg[m*6+0];
    float t1 = tg[m*6+1];
    float tx = tg[m*6+2] * fW;
    float ty = tg[m*6+3] * fW;
    float tw = tg[m*6+4] * fW;
    float th = tg[m*6+5] * fW;

    float aw = c_anch[lev][a][0];
    float ah = c_anch[lev][a][1];
    float rw = aw / tw, rh = ah / th;
    float mr = fmaxf(fmaxf(rw, 1.f/rw), fmaxf(rh, 1.f/rh));
    bool bm = mr < 4.0f;    // warp-uniform

    float lbox_c = 0.f, cls_c = 0.f, corr_c = 0.f;
    int cnt_c = 0;
    int cellsOut[3]; int nCellsOut = 0;

    if (bm){   // warp-uniform branch: all lanes enter together
        int gx0 = (int)floorf(tx);
        int gy0 = (int)floorf(ty);
        float remx = tx - (float)gx0;
        float remy = ty - (float)gy0;

        // x neighbor: exactly one of left/right may fire (rem==0.5 -> none)
        bool xleft = remx < 0.5f;
        bool fxv = xleft ? (tx > 1.0f) : ((remx > 0.5f) && (tx < fW - 1.0f));
        int  gx1 = xleft ? gx0 - 1 : gx0 + 1;
        // y neighbor
        bool ytop = remy < 0.5f;
        bool fyv = ytop ? (ty > 1.0f) : ((remy > 0.5f) && (ty < fW - 1.0f));
        int  gy1 = ytop ? gy0 - 1 : gy0 + 1;

        int gxc0 = min(max(gx0, 0), W-1), gyc0 = min(max(gy0, 0), W-1);
        int gxc1 = min(max(gx1, 0), W-1), gyc1 = min(max(gy1, 0), W-1);
        int img = min(max((int)t0, 0), NIMG-1);
        int cls = (int)t1;

        const float* P = (lev==0) ? p0 : ((lev==1) ? p1 : p2);
        const float* plane = P + (size_t)(img*255 + a*85) * HW;
        const float* b0 = plane + gyc0 * W + gxc0;   // center
        const float* b1 = plane + gyc0 * W + gxc1;   // x-neighbor (same row)
        const float* b2 = plane + gyc1 * W + gxc0;   // y-neighbor (same col)

        // ---- class logits for up to 3 cells; lane covers c, c+32, c+64 ----
        float s0=0.f, s1=0.f, s2=0.f, p0v=0.f, p1v=0.f, p2v=0.f;
        #pragma unroll
        for (int i = 0; i < 3; i++){
            int c = lane + 32*i;
            if (c < NCLS){
                size_t o = (size_t)(5 + c) * HW;
                float v0 = __ldg(b0 + o);
                float v1 = fxv ? __ldg(b1 + o) : 0.f;
                float v2 = fyv ? __ldg(b2 + o) : 0.f;
                s0 += sp_(v0); if (c == cls) p0v = v0;
                if (fxv){ s1 += sp_(v1); if (c == cls) p1v = v1; }
                if (fyv){ s2 += sp_(v2); if (c == cls) p2v = v2; }
            }
        }
        // ---- box+obj logits: lanes 0-4 cell0, 8-12 cellx, 16-20 celly ----
        float opv = 0.f;
        if (lane < 5)                          opv = __ldg(b0 + (size_t)lane * HW);
        else if (lane >= 8  && lane < 13 && fxv) opv = __ldg(b1 + (size_t)(lane-8)  * HW);
        else if (lane >= 16 && lane < 21 && fyv) opv = __ldg(b2 + (size_t)(lane-16) * HW);

        s0 = wsum_(s0); p0v = wsum_(p0v);
        s1 = wsum_(s1); p1v = wsum_(p1v);
        s2 = wsum_(s2); p2v = wsum_(p2v);

        // ---- extract per-cell logits WARP-WIDE (convergent shuffles) ----
        float q[3][5];
        #pragma unroll
        for (int k = 0; k < 3; k++){
            #pragma unroll
            for (int j = 0; j < 5; j++)
                q[k][j] = __shfl_sync(0xffffffffu, opv, k*8 + j);
        }

        // ---- scalar epilogue on lane 0 only (NO sync primitives inside) ----
        if (lane == 0){
            int lvoff = (lev==0) ? 0 : ((lev==1) ? CELLS0 : (CELLS0+CELLS1));
            int planeOff = lvoff + (img*3 + a) * HW;
            cnt_c = 1 + (fxv ? 1 : 0) + (fyv ? 1 : 0);

            #pragma unroll
            for (int k = 0; k < 3; k++){
                bool valid = (k==0) || (k==1 && fxv) || (k==2 && fyv);
                if (!valid) continue;

                float gox, goy; int cx, cy;
                if (k == 0){ gox = remx;               goy = remy;               cx = gxc0; cy = gyc0; }
                else if (k == 1){ gox = tx-(float)gx1; goy = remy;               cx = gxc1; cy = gyc0; }
                else {            gox = remx;          goy = ty-(float)gy1;      cx = gxc0; cy = gyc1; }

                float px = sig_(q[k][0]) * 2.f - 0.5f;
                float py = sig_(q[k][1]) * 2.f - 0.5f;
                float sw = sig_(q[k][2]) * 2.f;
                float sh2= sig_(q[k][3]) * 2.f;
                float xob= q[k][4];
                float pw = sw * sw * aw;
                float ph = sh2 * sh2 * ah;
                float gi = giou_(px, py, pw, ph, gox, goy, tw, th);
                lbox_c += 1.f - gi;
                float ssum = (k==0) ? s0 : ((k==1) ? s1 : s2);
                float pick = (k==0) ? p0v : ((k==1) ? p1v : p2v);
                cls_c += ssum - pick;

                float ov = fmaxf(gi, 0.f);
                if (ov > 0.f){
                    int cell = planeOff + cy * W + cx;
                    unsigned old = atomicMax(&g_objmax[cell], __float_as_uint(ov));
                    float oldf = __uint_as_float(old);
                    if (ov > oldf){
                        corr_c += (ov - oldf) * xob;     // telescopes to max*x
                        if (old == 0u) cellsOut[nCellsOut++] = cell;
                    }
                }
            }
        }
    }

    // ---- block reduction (blocks are level-homogeneous: 3072 % 8 == 0) ----
    __shared__ float sh_lb[8], sh_lc[8], sh_co[8];
    __shared__ int   sh_cn[8], sh_nc[8], sh_cell[8][3];
    if (lane == 0){
        sh_lb[wib] = lbox_c; sh_lc[wib] = cls_c; sh_co[wib] = corr_c;
        sh_cn[wib] = cnt_c;  sh_nc[wib] = nCellsOut;
        for (int i = 0; i < nCellsOut; i++) sh_cell[wib][i] = cellsOut[i];
    }
    __syncthreads();
    if (tid == 0){
        int lev2 = gid / (MT * NA);
        float lb = 0.f, lc = 0.f, co = 0.f; int cn = 0, nv = 0;
        int cells[24];
        #pragma unroll
        for (int i = 0; i < 8; i++){
            lb += sh_lb[i]; lc += sh_lc[i]; co += sh_co[i]; cn += sh_cn[i];
            for (int j = 0; j < sh_nc[i]; j++) cells[nv++] = sh_cell[i][j];
        }
        if (cn){
            atomicAdd(&g_acc[lev2],     (double)lb);
            atomicAdd(&g_acc[3 + lev2], (double)lc);
            atomicAdd(&g_cnt[lev2], cn);
        }
        if (co != 0.f) atomicAdd(&g_acc[9 + lev2], (double)co);
        if (nv){
            int bse = atomicAdd(&g_nflag, nv);
            for (int i = 0; i < nv; i++) g_cellList[bse + i] = cells[i];
        }
    }
}

// ============================ Kernel B ======================================
// 64 blocks: zero the listed g_objmax cells. g_nflag is read-only here.
__global__ __launch_bounds__(256) void k_zero()
{
    int n = min(g_nflag, TOTCELLS);
    for (int i = blockIdx.x * 256 + threadIdx.x; i < n; i += 64 * 256)
        g_objmax[g_cellList[i]] = 0u;
}

// ============================ Kernel C ======================================
// 1 warp: finalize scalar and reset all state (strictly after k_zero).
__global__ void k_fin(float* __restrict__ out)
{
    const int tid = threadIdx.x;
    if (tid == 0){
        const double cells[3] = {614400.0, 153600.0, 38400.0};
        const double bal[3]   = {4.0, 1.0, 0.4};
        double lbox = 0.0, lcls = 0.0, lobj = 0.0;
        #pragma unroll
        for (int l = 0; l < 3; l++){
            double cnt = (g_cnt[l] > 0) ? (double)g_cnt[l] : 1.0;
            lbox += g_acc[l] / cnt;
            lcls += g_acc[3 + l] / (cnt * (double)NCLS);
            lobj += ((g_acc[6 + l] - g_acc[9 + l]) / cells[l]) * bal[l];
        }
        out[0] = (float)((0.05 * lbox + 0.5 * lcls + lobj) * 32.0);
    }
    // reset state for next graph replay
    if (tid < 12) g_acc[tid] = 0.0;
    if (tid >= 12 && tid < 15) g_cnt[tid - 12] = 0;
    if (tid == 15) g_nflag = 0;
}

// ---------------------------------------------------------------------------
extern "C" void kernel_launch(void* const* d_in, const int* in_sizes, int n_in,
                              void* d_out, int out_size){
    const float* p0 = (const float*)d_in[0];
    const float* p1 = (const float*)d_in[1];
    const float* p2 = (const float*)d_in[2];
    const float* tg = (const float*)d_in[3];
    float* out = (float*)d_out;
    (void)in_sizes; (void)n_in; (void)out_size;

    k_main<<<GRID, 256>>>(p0, p1, p2, tg);
    k_zero<<<64, 256>>>();
    k_fin <<<1, 32>>>(out);
}

// round 13
// speedup vs baseline: 1.9155x; 1.1040x over previous
#include <cuda_runtime.h>

// ---------------------------------------------------------------------------
// ComputeLoss (YOLOv5-style), fixed shapes:
//   p0: (32,255,80,80)  p1: (32,255,40,40)  p2: (32,255,20,20)
//   targets: (1024,6) = [img, cls, cx, cy, w, h]
// Output: one float32 scalar.
//
// 3 launches:
//   k_main : dense softplus(obj) stream + ONE WARP PER (lev,m,a) GROUP.
//            The <=3 flagged cells (center, x-, y-neighbor) are processed by
//            lanes 0/1/2 IN PARALLEL (parallel atomicMax, distributed regs).
//   k_zero : 64 blocks zero the listed g_objmax cells
//   k_fin  : finalize scalar, reset state.
// ---------------------------------------------------------------------------

#define NIMG 32
#define NA   3
#define NCLS 80
#define MT   1024
#define CELLS0 (NIMG*NA*80*80)    // 614400
#define CELLS1 (NIMG*NA*40*40)    // 153600
#define CELLS2 (NIMG*NA*20*20)    // 38400
#define CELLS_TOT (CELLS0+CELLS1+CELLS2)   // 806400
#define TOTCELLS (3*3*MT*3)       // list capacity: 3 cells per group max

#define OBJ_GROUPS (CELLS_TOT/4)              // 201600 float4 groups
#define OBJ_BLOCKS ((OBJ_GROUPS + 255)/256)   // 788
#define NGRP (3*MT*NA)                        // 9216 groups (lev,m,a)
#define CAND_BLOCKS (NGRP/8)                  // 1152
#define GRID (OBJ_BLOCKS + CAND_BLOCKS)       // 1940

#define FULLM 0xffffffffu

__constant__ float c_anch[3][3][2] = {
  {{1.25f,1.625f},{2.0f,3.75f},{4.125f,2.875f}},
  {{1.875f,3.8125f},{3.875f,2.8125f},{3.6875f,7.4375f}},
  {{3.625f,2.8125f},{4.875f,6.1875f},{11.65625f,10.1875f}}
};

// per-cell objectness max (float bits >= 0). Zero at module load; k_zero
// zeroes every touched cell each launch (list-driven).
__device__ unsigned g_objmax[CELLS_TOT];
__device__ int   g_cellList[TOTCELLS];
__device__ int   g_nflag;
// [0..2]=lbox, [3..5]=cls, [6..8]=obj_softplus, [9..11]=obj_corr
__device__ double g_acc[12];
__device__ int g_cnt[3];

__device__ __forceinline__ float sp_(float x){          // softplus (fast-math)
    return fmaxf(x, 0.f) + __logf(1.f + __expf(-fabsf(x)));
}
__device__ __forceinline__ float sig_(float x){
    return 1.f / (1.f + __expf(-x));
}

__device__ __forceinline__ float giou_(float px,float py,float pw,float ph,
                                       float gx,float gy,float gw,float gh){
    const float eps = 1e-7f;
    float px1 = px - pw*0.5f, py1 = py - ph*0.5f;
    float px2 = px + pw*0.5f, py2 = py + ph*0.5f;
    float qx1 = gx - gw*0.5f, qy1 = gy - gh*0.5f;
    float qx2 = gx + gw*0.5f, qy2 = gy + gh*0.5f;
    float iw = fmaxf(fminf(px2,qx2) - fmaxf(px1,qx1), 0.f);
    float ih = fmaxf(fminf(py2,qy2) - fmaxf(py1,qy1), 0.f);
    float inter = iw * ih;
    float uni = pw*ph + gw*gh - inter + eps;
    float iou = inter / uni;
    float cw = fmaxf(px2,qx2) - fminf(px1,qx1);
    float ch = fmaxf(py2,qy2) - fminf(py1,qy1);
    float ca = cw*ch + eps;
    return iou - (ca - uni) / ca;
}

// warp butterfly sum (warp-wide, convergent)
__device__ __forceinline__ float wsum_(float v){
    #pragma unroll
    for (int d = 16; d; d >>= 1) v += __shfl_xor_sync(FULLM, v, d);
    return v;
}

// ============================ Kernel A ======================================
__global__ __launch_bounds__(256, 5) void k_main(
        const float* __restrict__ p0, const float* __restrict__ p1,
        const float* __restrict__ p2, const float* __restrict__ tg)
{
    const int tid  = threadIdx.x;
    const int lane = tid & 31;
    const int wib  = tid >> 5;

    if (blockIdx.x < OBJ_BLOCKS){
        // ---------------- dense objectness softplus sum -------------------
        // warps are level-homogeneous (boundaries at g = 153600, 192000)
        int g = blockIdx.x * 256 + tid;
        float s = 0.f;
        int lev = 2;
        if (g < OBJ_GROUPS){
            int cell = g * 4;
            int base, HW;
            const float* P;
            if (cell < CELLS0){ lev = 0; base = cell;               HW = 6400; P = p0; }
            else if (cell < CELLS0 + CELLS1){ lev = 1; base = cell - CELLS0; HW = 1600; P = p1; }
            else { lev = 2; base = cell - (CELLS0 + CELLS1); HW = 400; P = p2; }
            int n_a = base / HW, hw = base - n_a * HW;
            int n = n_a / 3, a = n_a - n * 3;
            const float4 v = *reinterpret_cast<const float4*>(
                P + (size_t)(n*255 + a*85 + 4) * HW + hw);
            s = sp_(v.x) + sp_(v.y) + sp_(v.z) + sp_(v.w);
        }
        s = wsum_(s);
        __shared__ float sh[8];
        if (lane == 0) sh[wib] = s;
        __syncthreads();
        if (tid == 0){
            float t = sh[0]+sh[1]+sh[2]+sh[3]+sh[4]+sh[5]+sh[6]+sh[7];
            atomicAdd(&g_acc[6 + lev], (double)t);
        }
        return;
    }

    // ---------- candidate path: ONE WARP PER (lev, m, a) GROUP ------------
    int gid = ((blockIdx.x - OBJ_BLOCKS) * 256 + tid) >> 5;   // 0..9215
    int lev = gid / (MT * NA);
    int r   = gid - lev * (MT * NA);
    int m   = r / NA;
    int a   = r - m * NA;

    const int W  = (lev==0) ? 80 : ((lev==1) ? 40 : 20);
    const int HW = W * W;
    const float fW = (float)W;

    float t0 = tg[m*6+0];
    float t1 = tg[m*6+1];
    float tx = tg[m*6+2] * fW;
    float ty = tg[m*6+3] * fW;
    float tw = tg[m*6+4] * fW;
    float th = tg[m*6+5] * fW;

    float aw = c_anch[lev][a][0];
    float ah = c_anch[lev][a][1];
    float rw = aw / tw, rh = ah / th;
    float mr = fmaxf(fmaxf(rw, 1.f/rw), fmaxf(rh, 1.f/rh));
    bool bm = mr < 4.0f;    // warp-uniform

    float lbox_c = 0.f, cls_c = 0.f, corr_c = 0.f;
    int cnt_c = 0;
    int cellsOut[3]; int nCellsOut = 0;

    if (bm){   // warp-uniform branch: all lanes enter together
        int gx0 = (int)floorf(tx);
        int gy0 = (int)floorf(ty);
        float remx = tx - (float)gx0;
        float remy = ty - (float)gy0;

        // x neighbor: exactly one of left/right may fire (rem==0.5 -> none)
        bool xleft = remx < 0.5f;
        bool fxv = xleft ? (tx > 1.0f) : ((remx > 0.5f) && (tx < fW - 1.0f));
        int  gx1 = xleft ? gx0 - 1 : gx0 + 1;
        // y neighbor
        bool ytop = remy < 0.5f;
        bool fyv = ytop ? (ty > 1.0f) : ((remy > 0.5f) && (ty < fW - 1.0f));
        int  gy1 = ytop ? gy0 - 1 : gy0 + 1;

        int gxc0 = min(max(gx0, 0), W-1), gyc0 = min(max(gy0, 0), W-1);
        int gxc1 = min(max(gx1, 0), W-1), gyc1 = min(max(gy1, 0), W-1);
        int img = min(max((int)t0, 0), NIMG-1);
        int cls = (int)t1;

        const float* P = (lev==0) ? p0 : ((lev==1) ? p1 : p2);
        const float* plane = P + (size_t)(img*255 + a*85) * HW;
        const float* b0 = plane + gyc0 * W + gxc0;   // center
        const float* b1 = plane + gyc0 * W + gxc1;   // x-neighbor (same row)
        const float* b2 = plane + gyc1 * W + gxc0;   // y-neighbor (same col)

        // ---- class logits for up to 3 cells; lane covers c, c+32, c+64 ----
        float s0=0.f, s1=0.f, s2=0.f, p0v=0.f, p1v=0.f, p2v=0.f;
        #pragma unroll
        for (int i = 0; i < 3; i++){
            int c = lane + 32*i;
            if (c < NCLS){
                size_t o = (size_t)(5 + c) * HW;
                float v0 = __ldg(b0 + o);
                float v1 = fxv ? __ldg(b1 + o) : 0.f;
                float v2 = fyv ? __ldg(b2 + o) : 0.f;
                s0 += sp_(v0); if (c == cls) p0v = v0;
                if (fxv){ s1 += sp_(v1); if (c == cls) p1v = v1; }
                if (fyv){ s2 += sp_(v2); if (c == cls) p2v = v2; }
            }
        }
        // ---- box+obj logits: lanes 0-4 cell0, 8-12 cellx, 16-20 celly ----
        float opv = 0.f;
        if (lane < 5)                          opv = __ldg(b0 + (size_t)lane * HW);
        else if (lane >= 8  && lane < 13 && fxv) opv = __ldg(b1 + (size_t)(lane-8)  * HW);
        else if (lane >= 16 && lane < 21 && fyv) opv = __ldg(b2 + (size_t)(lane-16) * HW);

        s0 = wsum_(s0); p0v = wsum_(p0v);
        s1 = wsum_(s1); p1v = wsum_(p1v);
        s2 = wsum_(s2); p2v = wsum_(p2v);

        // ---- per-lane cell epilogue: lane k (0..2) owns cell k ----------
        // per-lane source index is legal for shfl; all lanes participate.
        int kk = (lane < 3) ? lane : 0;
        float q0 = __shfl_sync(FULLM, opv, kk*8 + 0);
        float q1 = __shfl_sync(FULLM, opv, kk*8 + 1);
        float q2 = __shfl_sync(FULLM, opv, kk*8 + 2);
        float q3 = __shfl_sync(FULLM, opv, kk*8 + 3);
        float xob= __shfl_sync(FULLM, opv, kk*8 + 4);

        bool kvalid = (lane == 0) || (lane == 1 && fxv) || (lane == 2 && fyv);
        float lb = 0.f, lc = 0.f, co = 0.f;
        int myCell = -1;

        if (kvalid){
            float gox = (kk == 1) ? (tx - (float)gx1) : remx;
            float goy = (kk == 2) ? (ty - (float)gy1) : remy;
            int   cx  = (kk == 1) ? gxc1 : gxc0;
            int   cy  = (kk == 2) ? gyc1 : gyc0;
            float ssum = (kk==0) ? s0 : ((kk==1) ? s1 : s2);
            float pick = (kk==0) ? p0v : ((kk==1) ? p1v : p2v);

            float px = sig_(q0) * 2.f - 0.5f;
            float py = sig_(q1) * 2.f - 0.5f;
            float sw = sig_(q2) * 2.f;
            float sh2= sig_(q3) * 2.f;
            float pw = sw * sw * aw;
            float ph = sh2 * sh2 * ah;
            float gi = giou_(px, py, pw, ph, gox, goy, tw, th);
            lb = 1.f - gi;
            lc = ssum - pick;

            float ov = fmaxf(gi, 0.f);
            if (ov > 0.f){
                int lvoff = (lev==0) ? 0 : ((lev==1) ? CELLS0 : (CELLS0+CELLS1));
                int cell = lvoff + (img*3 + a) * HW + cy * W + cx;
                unsigned old = atomicMax(&g_objmax[cell], __float_as_uint(ov));
                float oldf = __uint_as_float(old);
                if (ov > oldf){
                    co = (ov - oldf) * xob;          // telescopes to max*x
                    if (old == 0u) myCell = cell;    // first raiser lists cell
                }
            }
        }

        // warp-wide reductions (convergent; non-valid lanes contribute 0)
        lbox_c = wsum_(lb);
        cls_c  = wsum_(lc);
        corr_c = wsum_(co);
        cnt_c  = 1 + (fxv ? 1 : 0) + (fyv ? 1 : 0);

        // collect up to 3 listed cells onto lane 0 (warp-wide shuffles)
        int c1 = __shfl_sync(FULLM, myCell, 1);
        int c2 = __shfl_sync(FULLM, myCell, 2);
        if (lane == 0){
            if (myCell >= 0) cellsOut[nCellsOut++] = myCell;
            if (c1 >= 0)     cellsOut[nCellsOut++] = c1;
            if (c2 >= 0)     cellsOut[nCellsOut++] = c2;
        }
    }

    // ---- block reduction (blocks are level-homogeneous: 3072 % 8 == 0) ----
    __shared__ float sh_lb[8], sh_lc[8], sh_co[8];
    __shared__ int   sh_cn[8], sh_nc[8], sh_cell[8][3];
    if (lane == 0){
        sh_lb[wib] = lbox_c; sh_lc[wib] = cls_c; sh_co[wib] = corr_c;
        sh_cn[wib] = cnt_c;  sh_nc[wib] = nCellsOut;
        for (int i = 0; i < nCellsOut; i++) sh_cell[wib][i] = cellsOut[i];
    }
    __syncthreads();
    if (tid == 0){
        int lev2 = gid / (MT * NA);
        float lb = 0.f, lc = 0.f, co = 0.f; int cn = 0, nv = 0;
        int cells[24];
        #pragma unroll
        for (int i = 0; i < 8; i++){
            lb += sh_lb[i]; lc += sh_lc[i]; co += sh_co[i]; cn += sh_cn[i];
            for (int j = 0; j < sh_nc[i]; j++) cells[nv++] = sh_cell[i][j];
        }
        if (cn){
            atomicAdd(&g_acc[lev2],     (double)lb);
            atomicAdd(&g_acc[3 + lev2], (double)lc);
            atomicAdd(&g_cnt[lev2], cn);
        }
        if (co != 0.f) atomicAdd(&g_acc[9 + lev2], (double)co);
        if (nv){
            int bse = atomicAdd(&g_nflag, nv);
            for (int i = 0; i < nv; i++) g_cellList[bse + i] = cells[i];
        }
    }
}

// ============================ Kernel B ======================================
// 64 blocks: zero the listed g_objmax cells. g_nflag is read-only here.
__global__ __launch_bounds__(256) void k_zero()
{
    int n = min(g_nflag, TOTCELLS);
    for (int i = blockIdx.x * 256 + threadIdx.x; i < n; i += 64 * 256)
        g_objmax[g_cellList[i]] = 0u;
}

// ============================ Kernel C ======================================
// 1 warp: finalize scalar and reset all state (strictly after k_zero).
__global__ void k_fin(float* __restrict__ out)
{
    const int tid = threadIdx.x;
    if (tid == 0){
        const double cells[3] = {614400.0, 153600.0, 38400.0};
        const double bal[3]   = {4.0, 1.0, 0.4};
        double lbox = 0.0, lcls = 0.0, lobj = 0.0;
        #pragma unroll
        for (int l = 0; l < 3; l++){
            double cnt = (g_cnt[l] > 0) ? (double)g_cnt[l] : 1.0;
            lbox += g_acc[l] / cnt;
            lcls += g_acc[3 + l] / (cnt * (double)NCLS);
            lobj += ((g_acc[6 + l] - g_acc[9 + l]) / cells[l]) * bal[l];
        }
        out[0] = (float)((0.05 * lbox + 0.5 * lcls + lobj) * 32.0);
    }
    // reset state for next graph replay
    if (tid < 12) g_acc[tid] = 0.0;
    if (tid >= 12 && tid < 15) g_cnt[tid - 12] = 0;
    if (tid == 15) g_nflag = 0;
}

// ---------------------------------------------------------------------------
extern "C" void kernel_launch(void* const* d_in, const int* in_sizes, int n_in,
                              void* d_out, int out_size){
    const float* p0 = (const float*)d_in[0];
    const float* p1 = (const float*)d_in[1];
    const float* p2 = (const float*)d_in[2];
    const float* tg = (const float*)d_in[3];
    float* out = (float*)d_out;
    (void)in_sizes; (void)n_in; (void)out_size;

    k_main<<<GRID, 256>>>(p0, p1, p2, tg);
    k_zero<<<64, 256>>>();
    k_fin <<<1, 32>>>(out);
}